// round 10
// baseline (speedup 1.0000x reference)
#include <cuda_runtime.h>
#include <cuda_bf16.h>
#include <stdint.h>

#define NTOK   16384
#define DIM    2048
#define NE     64
#define KTOP   8
#define ALPHA_C 0.001f

#define TM     128                 // tokens per CTA
#define NT     256                 // threads per CTA (8 warps, m16 each)
#define KC     64                  // k per chunk
#define NBLK   (NTOK / TM)         // 128 CTAs
#define NCH    (DIM / KC)          // 32 chunks
#define TAU    1e-4f               // near-tie fallback threshold (logit gap)

// smem tiles: bf16, padded pitch 72 bf16 = 144B  (ldmatrix rows -> banks 0,4,..,28)
#define APB    144
#define ABYTES (128 * APB)         // 18432
#define BBYTES (64 * APB)          // 9216
#define PERBUF (2 * ABYTES + 2 * BBYTES)   // 55296
#define AOFF(b, t) ((b) * PERBUF + (t) * ABYTES)
#define BOFF(b, t) ((b) * PERBUF + 2 * ABYTES + (t) * BBYTES)
#define DYN_BYTES (2 * PERBUF + 1024)

__device__ float g_cnt_part[NBLK][NE];
__device__ float g_prob_part[NBLK][NE];
__device__ unsigned int g_sync = 0;   // atomicInc wraps each launch -> graph-replay safe

static __device__ __forceinline__ uint32_t smem_u32(const void* p) {
    uint32_t a;
    asm("{ .reg .u64 t; cvta.to.shared.u64 t, %1; cvt.u32.u64 %0, t; }" : "=r"(a) : "l"(p));
    return a;
}

// baseline-PTX tensor ops (sm_75/80+, valid for plain sm_103 target)
#define LDSM4(r, a) \
    asm volatile("ldmatrix.sync.aligned.m8n8.x4.shared.b16 {%0,%1,%2,%3}, [%4];" \
        : "=r"((r)[0]), "=r"((r)[1]), "=r"((r)[2]), "=r"((r)[3]) : "r"(a))

#define MMA(d, a, b) \
    asm volatile("mma.sync.aligned.m16n8k16.row.col.f32.bf16.bf16.f32 " \
        "{%0,%1,%2,%3}, {%4,%5,%6,%7}, {%8,%9}, {%0,%1,%2,%3};" \
        : "+f"((d)[0]), "+f"((d)[1]), "+f"((d)[2]), "+f"((d)[3]) \
        : "r"((a)[0]), "r"((a)[1]), "r"((a)[2]), "r"((a)[3]), "r"((b)[0]), "r"((b)[1]))

// fp32x4 -> bf16 hi (4) + bf16 lo (4), pairwise cvt (k order preserved: .x = low half)
static __device__ __forceinline__ void split4(float4 v, uint2& hi, uint2& lo) {
    __nv_bfloat162 h0 = __float22bfloat162_rn(make_float2(v.x, v.y));
    __nv_bfloat162 h1 = __float22bfloat162_rn(make_float2(v.z, v.w));
    float2 f0 = __bfloat1622float2(h0);
    float2 f1 = __bfloat1622float2(h1);
    __nv_bfloat162 l0 = __float22bfloat162_rn(make_float2(v.x - f0.x, v.y - f0.y));
    __nv_bfloat162 l1 = __float22bfloat162_rn(make_float2(v.z - f1.x, v.w - f1.y));
    hi.x = *reinterpret_cast<uint32_t*>(&h0);
    hi.y = *reinterpret_cast<uint32_t*>(&h1);
    lo.x = *reinterpret_cast<uint32_t*>(&l0);
    lo.y = *reinterpret_cast<uint32_t*>(&l1);
}

// ---- chunk stages ----
static __device__ __forceinline__ void ldg_chunk(const float* Hb, const float* W, int c, int tid,
                                                 float4 (&ha)[8], float4 (&wa)[4]) {
    const float* hp = Hb + c * KC;
#pragma unroll
    for (int g = 0; g < 8; g++) {                 // A: 128 rows x 16 float4
        int flat = tid + 256 * g, row = flat >> 4, f4 = flat & 15;
        ha[g] = *(const float4*)(hp + (size_t)row * DIM + f4 * 4);
    }
    const float* wp = W + c * KC;
#pragma unroll
    for (int g = 0; g < 4; g++) {                 // B: 64 rows x 16 float4
        int flat = tid + 256 * g, row = flat >> 4, f4 = flat & 15;
        wa[g] = *(const float4*)(wp + (size_t)row * DIM + f4 * 4);
    }
}
static __device__ __forceinline__ void sts_chunk(char* base, int buf, int tid,
                                                 const float4 (&ha)[8], const float4 (&wa)[4]) {
#pragma unroll
    for (int g = 0; g < 8; g++) {
        int flat = tid + 256 * g, row = flat >> 4, f4 = flat & 15;
        uint2 hi, lo; split4(ha[g], hi, lo);
        int off = row * APB + f4 * 8;
        *(uint2*)(base + AOFF(buf, 0) + off) = hi;
        *(uint2*)(base + AOFF(buf, 1) + off) = lo;
    }
#pragma unroll
    for (int g = 0; g < 4; g++) {
        int flat = tid + 256 * g, row = flat >> 4, f4 = flat & 15;
        uint2 hi, lo; split4(wa[g], hi, lo);
        int off = row * APB + f4 * 8;
        *(uint2*)(base + BOFF(buf, 0) + off) = hi;
        *(uint2*)(base + BOFF(buf, 1) + off) = lo;
    }
}

// v2: chain-free MMA order + fragment double-buffering.
// Per-accumulator k/term order identical to R9 (hh, hl, lh per k16-step) ->
// logits bit-identical to the validated R9 kernel.
static __device__ __forceinline__ void compute_chunk(uint32_t dynb32, int buf, int wid, int lane,
                                                     float (&acc)[8][4]) {
    const uint32_t aHi = dynb32 + AOFF(buf, 0), aLo = dynb32 + AOFF(buf, 1);
    const uint32_t bHi = dynb32 + BOFF(buf, 0), bLo = dynb32 + BOFF(buf, 1);
    // A x4 tiles: (r0-7,k0-7)(r8-15,k0-7)(r0-7,k8-15)(r8-15,k8-15)
    const uint32_t aRow = (uint32_t)((wid * 16 + (lane & 15)) * APB + (lane >> 4) * 16);
    // B x4 tiles: two n8 tiles x {k0-7, k8-15}
    const uint32_t bRow = (uint32_t)(((lane & 7) + ((lane >> 4) & 1) * 8) * APB +
                                     ((lane >> 3) & 1) * 16);

    uint32_t ah[2][4], al[2][4], bh[2][4][4], bl[2][4][4];

    // preload k16-step 0 fragments
    LDSM4(ah[0], aHi + aRow);
    LDSM4(al[0], aLo + aRow);
#pragma unroll
    for (int jp = 0; jp < 4; jp++) {
        LDSM4(bh[0][jp], bHi + (uint32_t)(jp * 16 * APB) + bRow);
        LDSM4(bl[0][jp], bLo + (uint32_t)(jp * 16 * APB) + bRow);
    }
#pragma unroll
    for (int s = 0; s < 4; s++) {
        const int cu = s & 1, nx = cu ^ 1;
        if (s < 3) {   // prefetch next step's fragments under this step's MMAs
            const uint32_t so = (uint32_t)((s + 1) * 32);
            LDSM4(ah[nx], aHi + aRow + so);
            LDSM4(al[nx], aLo + aRow + so);
#pragma unroll
            for (int jp = 0; jp < 4; jp++) {
                LDSM4(bh[nx][jp], bHi + (uint32_t)(jp * 16 * APB) + bRow + so);
                LDSM4(bl[nx][jp], bLo + (uint32_t)(jp * 16 * APB) + bRow + so);
            }
        }
        // term-major: same-accumulator revisit distance = 8 instructions (no RAW chains)
#pragma unroll
        for (int jp = 0; jp < 4; jp++) {                       // hh
            MMA(acc[2 * jp],     ah[cu], bh[cu][jp]);
            MMA(acc[2 * jp + 1], ah[cu], bh[cu][jp] + 2);
        }
#pragma unroll
        for (int jp = 0; jp < 4; jp++) {                       // hl
            MMA(acc[2 * jp],     ah[cu], bl[cu][jp]);
            MMA(acc[2 * jp + 1], ah[cu], bl[cu][jp] + 2);
        }
#pragma unroll
        for (int jp = 0; jp < 4; jp++) {                       // lh
            MMA(acc[2 * jp],     al[cu], bh[cu][jp]);
            MMA(acc[2 * jp + 1], al[cu], bh[cu][jp] + 2);
        }
    }
}

__global__ __launch_bounds__(NT, 1)
void gate_kernel(const float* __restrict__ H, const float* __restrict__ W,
                 float* __restrict__ out, int out_size)
{
    extern __shared__ char dynsm[];
    __shared__ float logits[TM][NE + 1];
    __shared__ float rinv[TM];
    __shared__ float sm_cnt[NE];
    __shared__ float pr[4][NE];
    __shared__ float rc[4][NE], rp[4][NE];
    __shared__ unsigned int is_last;
    __shared__ int fb_cnt;
    __shared__ int fb_list[TM];

    const int tid  = threadIdx.x;
    const int blk  = blockIdx.x;
    const int wid  = tid >> 5;
    const int lane = tid & 31;
    char* base = (char*)((((uintptr_t)dynsm) + 1023) & ~(uintptr_t)1023);
    const uint32_t dynb32 = smem_u32(base);

    if (tid == 0) fb_cnt = 0;
    if (tid < NE) sm_cnt[tid] = 0.f;

    float acc[8][4];
#pragma unroll
    for (int j = 0; j < 8; j++)
#pragma unroll
        for (int q = 0; q < 4; q++) acc[j][q] = 0.f;

    const float* Hb = H + (size_t)blk * TM * DIM;

    // -------- GEMM: 3-term split-bf16 via HMMA, fp32 accumulation --------
    float4 ha[8]; float4 wa[4];
    ldg_chunk(Hb, W, 0, tid, ha, wa);
    sts_chunk(base, 0, tid, ha, wa);
    for (int c = 0; c < NCH; c++) {
        const bool more = (c + 1 < NCH);
        if (more) ldg_chunk(Hb, W, c + 1, tid, ha, wa);
        // one barrier/chunk: publishes STS(c); STS(c+1) below overwrites the buffer
        // consumed by compute(c-1), which every thread finished before this barrier.
        __syncthreads();
        compute_chunk(dynb32, c & 1, wid, lane, acc);
        if (more) sts_chunk(base, (c + 1) & 1, tid, ha, wa);
    }

    // -------- fragments -> logits smem --------
    {
        const int r = lane >> 2, cp = (lane & 3) * 2;
#pragma unroll
        for (int j = 0; j < 8; j++) {
            logits[wid * 16 + r][j * 8 + cp]         = acc[j][0];
            logits[wid * 16 + r][j * 8 + cp + 1]     = acc[j][1];
            logits[wid * 16 + r + 8][j * 8 + cp]     = acc[j][2];
            logits[wid * 16 + r + 8][j * 8 + cp + 1] = acc[j][3];
        }
    }
    __syncthreads();

    // -------- near-tie detection: any adjacent gap in top-9 below TAU --------
    if (tid < TM) {
        float v[9];
#pragma unroll
        for (int j = 0; j < 9; j++) v[j] = -1e30f;
        for (int e = 0; e < NE; e++) {
            float nv = logits[tid][e];
#pragma unroll
            for (int j = 0; j < 9; j++) {
                if (nv > v[j]) { float t = v[j]; v[j] = nv; nv = t; }
            }
        }
        float mingap = 1e30f;
#pragma unroll
        for (int j = 0; j < 8; j++) mingap = fminf(mingap, v[j] - v[j + 1]);
        if (mingap < TAU) {
            int ix = atomicAdd(&fb_cnt, 1);
            fb_list[ix] = tid;
        }
    }
    __syncthreads();

    // -------- exact fp32 sequential-k fallback (matches R0 bit-for-bit), 4 tokens/pass --------
    {
        const int nfb = fb_cnt;
        for (int f0 = 0; f0 < nfb; f0 += 4) {
            const int fi = f0 + (tid >> 6);
            if (fi < nfb) {
                const int t = fb_list[fi];
                const int e = tid & 63;
                const float* hr = H + (size_t)(blk * TM + t) * DIM;
                const float* wr = W + (size_t)e * DIM;
                float a = 0.f;
                for (int k = 0; k < DIM; k += 4) {
                    float4 hv = *(const float4*)(hr + k);
                    float4 wv = *(const float4*)(wr + k);
                    a = fmaf(hv.x, wv.x, a);
                    a = fmaf(hv.y, wv.y, a);
                    a = fmaf(hv.z, wv.z, a);
                    a = fmaf(hv.w, wv.w, a);
                }
                logits[t][e] = a;
            }
        }
    }
    __syncthreads();

    // -------- per-token softmax + top-8 (proven R0 pipeline) --------
    if (tid < TM) {
        float m = -1e30f;
        for (int e = 0; e < NE; e++) m = fmaxf(m, logits[tid][e]);

        float s = 0.f;
        float val[KTOP]; int idx[KTOP];
#pragma unroll
        for (int j = 0; j < KTOP; j++) { val[j] = -1.f; idx[j] = 0; }
        for (int e = 0; e < NE; e++) {
            float ex = __expf(logits[tid][e] - m);
            logits[tid][e] = ex;   // stash exp for mean-prob pass
            s += ex;
            float nv = ex; int ni = e;
#pragma unroll
            for (int j = 0; j < KTOP; j++) {
                if (nv > val[j]) {
                    float tv = val[j]; val[j] = nv; nv = tv;
                    int   ti = idx[j]; idx[j] = ni; ni = ti;
                }
            }
        }
        rinv[tid] = 1.f / s;

        float ts = 0.f;
#pragma unroll
        for (int j = 0; j < KTOP; j++) ts += val[j];
        const float tinv = 1.f / ts;

        const int gt = blk * TM + tid;
        float* ow = out + (size_t)gt * KTOP;
        float* oi = out + (size_t)NTOK * KTOP + (size_t)gt * KTOP;
#pragma unroll
        for (int j = 0; j < KTOP; j++) {
            ow[j] = val[j] * tinv;
            oi[j] = (float)idx[j];
            atomicAdd(&sm_cnt[idx[j]], 1.f);  // integer counts: order-exact
        }
    }
    __syncthreads();

    // -------- per-block mean-prob partial (4 parts x 32 tokens) --------
    {
        const int e = tid & 63;
        const int p = tid >> 6;
        float sacc = 0.f;
        for (int t = p * 32; t < p * 32 + 32; t++)
            sacc += logits[t][e] * rinv[t];
        pr[p][e] = sacc;
    }
    __syncthreads();
    if (tid < NE) {
        g_prob_part[blk][tid] = pr[0][tid] + pr[1][tid] + pr[2][tid] + pr[3][tid];
        g_cnt_part[blk][tid]  = sm_cnt[tid];
    }

    // -------- last block finalizes the aux loss --------
    __threadfence();
    if (tid == 0)
        is_last = (atomicInc(&g_sync, NBLK - 1) == NBLK - 1);
    __syncthreads();
    if (is_last) {
        const int e = tid & 63;
        const int p = tid >> 6;       // 4 parts x 32 blocks, fixed order
        float c = 0.f, pm = 0.f;
        for (int b = p * 32; b < p * 32 + 32; b++) {
            c  += g_cnt_part[b][e];
            pm += g_prob_part[b][e];
        }
        rc[p][e] = c; rp[p][e] = pm;
        __syncthreads();
        if (tid == 0) {
            float s = 0.f;
            for (int e2 = 0; e2 < NE; e2++) {
                float C = rc[0][e2] + rc[1][e2] + rc[2][e2] + rc[3][e2];
                float P = rp[0][e2] + rp[1][e2] + rp[2][e2] + rp[3][e2];
                s += (C / (float)(NTOK * KTOP)) * (P / (float)NTOK);
            }
            const int pos = NTOK * KTOP * 2;
            if (pos < out_size) out[pos] = ALPHA_C * (float)NE * s;
        }
    }
}

extern "C" void kernel_launch(void* const* d_in, const int* in_sizes, int n_in,
                              void* d_out, int out_size)
{
    const float* H = (const float*)d_in[0];   // hidden_states (16384, 2048) fp32
    const float* W = (const float*)d_in[1];   // weight (64, 2048) fp32
    float* out = (float*)d_out;

    cudaFuncSetAttribute(gate_kernel, cudaFuncAttributeMaxDynamicSharedMemorySize, DYN_BYTES);
    gate_kernel<<<NBLK, NT, DYN_BYTES>>>(H, W, out, out_size);
}

// round 11
// speedup vs baseline: 2.1629x; 2.1629x over previous
#include <cuda_runtime.h>
#include <cuda_bf16.h>
#include <stdint.h>

#define NTOK   16384
#define DIM    2048
#define NE     64
#define KTOP   8
#define ALPHA_C 0.001f

#define TM     64                  // tokens per CTA
#define NT     256                 // threads per CTA (8 warps: 4 M-rows x 2 N-halves)
#define KC     64                  // k per chunk
#define NBLK   (NTOK / TM)         // 256 CTAs -> 2 per SM
#define NCH    (DIM / KC)          // 32 chunks
#define TAU    1e-4f               // near-tie fallback threshold (logit gap)

// smem tiles: bf16, padded pitch 72 bf16 = 144B (ldmatrix rows -> banks 0,4,..,28)
#define APB    144
#define TBYTES (64 * APB)          // 9216 per (tile,term):  A 64 rows, B 64 rows
#define PERBUF (4 * TBYTES)        // A-hi, A-lo, B-hi, B-lo = 36864
#define AOFF(b, t) ((b) * PERBUF + (t) * TBYTES)
#define BOFF(b, t) ((b) * PERBUF + 2 * TBYTES + (t) * TBYTES)
#define DYN_BYTES (2 * PERBUF + 1024)

__device__ float g_cnt_part[NBLK][NE];
__device__ float g_prob_part[NBLK][NE];
__device__ unsigned int g_sync = 0;   // atomicInc wraps each launch -> graph-replay safe

static __device__ __forceinline__ uint32_t smem_u32(const void* p) {
    uint32_t a;
    asm("{ .reg .u64 t; cvta.to.shared.u64 t, %1; cvt.u32.u64 %0, t; }" : "=r"(a) : "l"(p));
    return a;
}

// baseline-PTX tensor ops (sm_75/80+, valid for plain sm_103 target)
#define LDSM4(r, a) \
    asm volatile("ldmatrix.sync.aligned.m8n8.x4.shared.b16 {%0,%1,%2,%3}, [%4];" \
        : "=r"((r)[0]), "=r"((r)[1]), "=r"((r)[2]), "=r"((r)[3]) : "r"(a))

#define MMA(d, a, b) \
    asm volatile("mma.sync.aligned.m16n8k16.row.col.f32.bf16.bf16.f32 " \
        "{%0,%1,%2,%3}, {%4,%5,%6,%7}, {%8,%9}, {%0,%1,%2,%3};" \
        : "+f"((d)[0]), "+f"((d)[1]), "+f"((d)[2]), "+f"((d)[3]) \
        : "r"((a)[0]), "r"((a)[1]), "r"((a)[2]), "r"((a)[3]), "r"((b)[0]), "r"((b)[1]))

// fp32x4 -> bf16 hi (4) + bf16 lo (4), pairwise cvt (k order preserved)
static __device__ __forceinline__ void split4(float4 v, uint2& hi, uint2& lo) {
    __nv_bfloat162 h0 = __float22bfloat162_rn(make_float2(v.x, v.y));
    __nv_bfloat162 h1 = __float22bfloat162_rn(make_float2(v.z, v.w));
    float2 f0 = __bfloat1622float2(h0);
    float2 f1 = __bfloat1622float2(h1);
    __nv_bfloat162 l0 = __float22bfloat162_rn(make_float2(v.x - f0.x, v.y - f0.y));
    __nv_bfloat162 l1 = __float22bfloat162_rn(make_float2(v.z - f1.x, v.w - f1.y));
    hi.x = *reinterpret_cast<uint32_t*>(&h0);
    hi.y = *reinterpret_cast<uint32_t*>(&h1);
    lo.x = *reinterpret_cast<uint32_t*>(&l0);
    lo.y = *reinterpret_cast<uint32_t*>(&l1);
}

// ---- chunk stages (TM=64: A and B are both 64 rows x 16 float4 -> 4 LDG/thread) ----
static __device__ __forceinline__ void ldg_chunk(const float* Hb, const float* W, int c, int tid,
                                                 float4 (&ha)[4], float4 (&wa)[4]) {
    const float* hp = Hb + c * KC;
    const float* wp = W + c * KC;
#pragma unroll
    for (int g = 0; g < 4; g++) {
        int flat = tid + 256 * g, row = flat >> 4, f4 = flat & 15;
        ha[g] = *(const float4*)(hp + (size_t)row * DIM + f4 * 4);
        wa[g] = *(const float4*)(wp + (size_t)row * DIM + f4 * 4);
    }
}
static __device__ __forceinline__ void sts_chunk(char* base, int buf, int tid,
                                                 const float4 (&ha)[4], const float4 (&wa)[4]) {
#pragma unroll
    for (int g = 0; g < 4; g++) {
        int flat = tid + 256 * g, row = flat >> 4, f4 = flat & 15;
        int off = row * APB + f4 * 8;
        uint2 hi, lo;
        split4(ha[g], hi, lo);
        *(uint2*)(base + AOFF(buf, 0) + off) = hi;
        *(uint2*)(base + AOFF(buf, 1) + off) = lo;
        split4(wa[g], hi, lo);
        *(uint2*)(base + BOFF(buf, 0) + off) = hi;
        *(uint2*)(base + BOFF(buf, 1) + off) = lo;
    }
}

// warp tile: m16 (rows (wid&3)*16) x n32 (cols (wid>>2)*32), 3-term split-bf16.
// Per-accumulator order per k16-step: hh, hl, lh — identical to validated R9.
static __device__ __forceinline__ void compute_chunk(uint32_t dynb32, int buf, int wid, int lane,
                                                     float (&acc)[4][4]) {
    const uint32_t aHi = dynb32 + AOFF(buf, 0), aLo = dynb32 + AOFF(buf, 1);
    const uint32_t bHi = dynb32 + BOFF(buf, 0), bLo = dynb32 + BOFF(buf, 1);
    const uint32_t aRow = (uint32_t)(((wid & 3) * 16 + (lane & 15)) * APB + (lane >> 4) * 16);
    const uint32_t bR0  = (uint32_t)(((wid >> 2) * 32 + (lane & 7) + ((lane >> 4) & 1) * 8) * APB +
                                     ((lane >> 3) & 1) * 16);
#pragma unroll
    for (int s = 0; s < 4; s++) {
        const uint32_t so = (uint32_t)(s * 32);
        uint32_t ah[4], al[4], bh[2][4], bl[2][4];
        LDSM4(ah, aHi + aRow + so);
        LDSM4(al, aLo + aRow + so);
#pragma unroll
        for (int jp = 0; jp < 2; jp++) {
            LDSM4(bh[jp], bHi + bR0 + (uint32_t)(jp * 16 * APB) + so);
            LDSM4(bl[jp], bLo + bR0 + (uint32_t)(jp * 16 * APB) + so);
        }
        // term-major: same-acc revisit distance 4 (no RAW chains)
#pragma unroll
        for (int jp = 0; jp < 2; jp++) {               // hh
            MMA(acc[2 * jp],     ah, bh[jp]);
            MMA(acc[2 * jp + 1], ah, bh[jp] + 2);
        }
#pragma unroll
        for (int jp = 0; jp < 2; jp++) {               // hl
            MMA(acc[2 * jp],     ah, bl[jp]);
            MMA(acc[2 * jp + 1], ah, bl[jp] + 2);
        }
#pragma unroll
        for (int jp = 0; jp < 2; jp++) {               // lh
            MMA(acc[2 * jp],     al, bh[jp]);
            MMA(acc[2 * jp + 1], al, bh[jp] + 2);
        }
    }
}

__global__ __launch_bounds__(NT, 2)
void gate_kernel(const float* __restrict__ H, const float* __restrict__ W,
                 float* __restrict__ out, int out_size)
{
    extern __shared__ char dynsm[];
    __shared__ float logits[TM][NE + 1];
    __shared__ float rinv[TM];
    __shared__ float sm_cnt[NE];
    __shared__ float pr[4][NE];
    __shared__ float rc[4][NE], rp[4][NE];
    __shared__ unsigned int is_last;
    __shared__ int fb_cnt;
    __shared__ int fb_list[TM];

    const int tid  = threadIdx.x;
    const int blk  = blockIdx.x;
    const int wid  = tid >> 5;
    const int lane = tid & 31;
    char* base = (char*)((((uintptr_t)dynsm) + 1023) & ~(uintptr_t)1023);
    const uint32_t dynb32 = smem_u32(base);

    if (tid == 0) fb_cnt = 0;
    if (tid < NE) sm_cnt[tid] = 0.f;

    float acc[4][4];
#pragma unroll
    for (int j = 0; j < 4; j++)
#pragma unroll
        for (int q = 0; q < 4; q++) acc[j][q] = 0.f;

    const float* Hb = H + (size_t)blk * TM * DIM;

    // -------- GEMM: 3-term split-bf16 via HMMA, fp32 accumulation --------
    float4 ha[4], wa[4];
    ldg_chunk(Hb, W, 0, tid, ha, wa);
    sts_chunk(base, 0, tid, ha, wa);
    for (int c = 0; c < NCH; c++) {
        const bool more = (c + 1 < NCH);
        if (more) ldg_chunk(Hb, W, c + 1, tid, ha, wa);
        // one barrier/chunk: publishes STS(c); STS(c+1) below overwrites the buffer
        // consumed by compute(c-1), which every thread finished before this barrier.
        __syncthreads();
        compute_chunk(dynb32, c & 1, wid, lane, acc);
        if (more) sts_chunk(base, (c + 1) & 1, tid, ha, wa);
    }

    // -------- fragments -> logits smem --------
    {
        const int r = (wid & 3) * 16 + (lane >> 2);
        const int cb = (wid >> 2) * 32 + (lane & 3) * 2;
#pragma unroll
        for (int j = 0; j < 4; j++) {
            logits[r][cb + j * 8]         = acc[j][0];
            logits[r][cb + j * 8 + 1]     = acc[j][1];
            logits[r + 8][cb + j * 8]     = acc[j][2];
            logits[r + 8][cb + j * 8 + 1] = acc[j][3];
        }
    }
    __syncthreads();

    // -------- near-tie detection: any adjacent gap in top-9 below TAU --------
    if (tid < TM) {
        float v[9];
#pragma unroll
        for (int j = 0; j < 9; j++) v[j] = -1e30f;
        for (int e = 0; e < NE; e++) {
            float nv = logits[tid][e];
#pragma unroll
            for (int j = 0; j < 9; j++) {
                if (nv > v[j]) { float t = v[j]; v[j] = nv; nv = t; }
            }
        }
        float mingap = 1e30f;
#pragma unroll
        for (int j = 0; j < 8; j++) mingap = fminf(mingap, v[j] - v[j + 1]);
        if (mingap < TAU) {
            int ix = atomicAdd(&fb_cnt, 1);
            fb_list[ix] = tid;
        }
    }
    __syncthreads();

    // -------- exact fp32 sequential-k fallback (matches R0 bit-for-bit), 4 tokens/pass --------
    {
        const int nfb = fb_cnt;
        for (int f0 = 0; f0 < nfb; f0 += 4) {
            const int fi = f0 + (tid >> 6);
            if (fi < nfb) {
                const int t = fb_list[fi];
                const int e = tid & 63;
                const float* hr = H + (size_t)(blk * TM + t) * DIM;
                const float* wr = W + (size_t)e * DIM;
                float a = 0.f;
                for (int k = 0; k < DIM; k += 4) {
                    float4 hv = *(const float4*)(hr + k);
                    float4 wv = *(const float4*)(wr + k);
                    a = fmaf(hv.x, wv.x, a);
                    a = fmaf(hv.y, wv.y, a);
                    a = fmaf(hv.z, wv.z, a);
                    a = fmaf(hv.w, wv.w, a);
                }
                logits[t][e] = a;
            }
        }
    }
    __syncthreads();

    // -------- per-token softmax + top-8 (proven R0 pipeline) --------
    if (tid < TM) {
        float m = -1e30f;
        for (int e = 0; e < NE; e++) m = fmaxf(m, logits[tid][e]);

        float s = 0.f;
        float val[KTOP]; int idx[KTOP];
#pragma unroll
        for (int j = 0; j < KTOP; j++) { val[j] = -1.f; idx[j] = 0; }
        for (int e = 0; e < NE; e++) {
            float ex = __expf(logits[tid][e] - m);
            logits[tid][e] = ex;   // stash exp for mean-prob pass
            s += ex;
            float nv = ex; int ni = e;
#pragma unroll
            for (int j = 0; j < KTOP; j++) {
                if (nv > val[j]) {
                    float tv = val[j]; val[j] = nv; nv = tv;
                    int   ti = idx[j]; idx[j] = ni; ni = ti;
                }
            }
        }
        rinv[tid] = 1.f / s;

        float ts = 0.f;
#pragma unroll
        for (int j = 0; j < KTOP; j++) ts += val[j];
        const float tinv = 1.f / ts;

        const int gt = blk * TM + tid;
        float* ow = out + (size_t)gt * KTOP;
        float* oi = out + (size_t)NTOK * KTOP + (size_t)gt * KTOP;
#pragma unroll
        for (int j = 0; j < KTOP; j++) {
            ow[j] = val[j] * tinv;
            oi[j] = (float)idx[j];
            atomicAdd(&sm_cnt[idx[j]], 1.f);  // integer counts: order-exact
        }
    }
    __syncthreads();

    // -------- per-block mean-prob partial (4 parts x 16 tokens) --------
    {
        const int e = tid & 63;
        const int p = tid >> 6;
        float sacc = 0.f;
        for (int t = p * 16; t < p * 16 + 16; t++)
            sacc += logits[t][e] * rinv[t];
        pr[p][e] = sacc;
    }
    __syncthreads();
    if (tid < NE) {
        g_prob_part[blk][tid] = pr[0][tid] + pr[1][tid] + pr[2][tid] + pr[3][tid];
        g_cnt_part[blk][tid]  = sm_cnt[tid];
    }

    // -------- last block finalizes the aux loss --------
    __threadfence();
    if (tid == 0)
        is_last = (atomicInc(&g_sync, NBLK - 1) == NBLK - 1);
    __syncthreads();
    if (is_last) {
        const int e = tid & 63;
        const int p = tid >> 6;       // 4 parts x 64 blocks, fixed order
        float c = 0.f, pm = 0.f;
        for (int b = p * 64; b < p * 64 + 64; b++) {
            c  += g_cnt_part[b][e];
            pm += g_prob_part[b][e];
        }
        rc[p][e] = c; rp[p][e] = pm;
        __syncthreads();
        if (tid == 0) {
            float s = 0.f;
            for (int e2 = 0; e2 < NE; e2++) {
                float C = rc[0][e2] + rc[1][e2] + rc[2][e2] + rc[3][e2];
                float P = rp[0][e2] + rp[1][e2] + rp[2][e2] + rp[3][e2];
                s += (C / (float)(NTOK * KTOP)) * (P / (float)NTOK);
            }
            const int pos = NTOK * KTOP * 2;
            if (pos < out_size) out[pos] = ALPHA_C * (float)NE * s;
        }
    }
}

extern "C" void kernel_launch(void* const* d_in, const int* in_sizes, int n_in,
                              void* d_out, int out_size)
{
    const float* H = (const float*)d_in[0];   // hidden_states (16384, 2048) fp32
    const float* W = (const float*)d_in[1];   // weight (64, 2048) fp32
    float* out = (float*)d_out;

    cudaFuncSetAttribute(gate_kernel, cudaFuncAttributeMaxDynamicSharedMemorySize, DYN_BYTES);
    gate_kernel<<<NBLK, NT, DYN_BYTES>>>(H, W, out, out_size);
}